// round 1
// baseline (speedup 1.0000x reference)
#include <cuda_runtime.h>
#include <math.h>

// Problem dims
#define NI 32
#define HD 64
#define WD 64
#define CI 128
#define CM 256
#define MROWS (NI*HD*WD)   // 131072

// Scratch for the yat-conv intermediate y: [N,H,W,256] fp32 = 134 MB.
// Device global (no runtime allocation, per harness rules).
__device__ float g_y[(size_t)MROWS * CM];

// ---------------------------------------------------------------------------
// Kernel 1: fused YAT conv.
//   dot  = implicit GEMM: M=131072 (n,h,w), N=256 (cout), K=1152 (kh,kw,cin)
//   asum = sum over patch of x^2  (folded into A-fragment reads)
//   bsum = sum over kernel of w^2 (folded into B-fragment reads)
//   y    = dot^2 / (asum + bsum - 2 dot + 1e-5) * (16/log1p(256))^alpha
// ---------------------------------------------------------------------------
__global__ __launch_bounds__(256)
void k1_yat(const float* __restrict__ x, const float* __restrict__ wy,
            const float* __restrict__ alphap)
{
    __shared__ float As[2][16][132];   // K-major, M across (padded)
    __shared__ float Bs[2][16][132];   // K-major, N across (padded)

    const int tid    = threadIdx.x;
    const int m_base = blockIdx.y * 128;
    const int c_base = blockIdx.x * 128;

    // A-load mapping: 128 rows x 4 float4 (K dir) = 512 float4, 2 per thread
    const int a_m = tid >> 2;          // 0..63 (+64 on 2nd)
    const int a_k = (tid & 3) * 4;     // 0,4,8,12
    // B-load mapping: 16 rows x 32 float4 = 512 float4, 2 per thread
    const int b_k = tid >> 5;          // 0..7 (+8 on 2nd)
    const int b_c = (tid & 31) * 4;    // 0..124
    const int ty  = tid >> 4, tx = tid & 15;

    float acc[8][8];
    #pragma unroll
    for (int i = 0; i < 8; i++)
        #pragma unroll
        for (int j = 0; j < 8; j++) acc[i][j] = 0.f;
    float asum[8] = {0.f,0.f,0.f,0.f,0.f,0.f,0.f,0.f};
    float bsum[8] = {0.f,0.f,0.f,0.f,0.f,0.f,0.f,0.f};

    // Per-row spatial coords for the two A rows this thread loads
    int n0[2], h0[2], w0[2];
    #pragma unroll
    for (int r = 0; r < 2; r++) {
        int m = m_base + a_m + r * 64;
        n0[r] = m >> 12; h0[r] = (m >> 6) & 63; w0[r] = m & 63;
    }

    const int NCH = (9 * CI) / 16;   // 72 K-chunks

    float4 ar[2], br[2];

    auto gload = [&](int chunk) {
        int kb  = chunk << 4;
        int khw = kb >> 7;             // 0..8  (kh*3+kw)
        int c0  = kb & 127;            // cin base within this khw
        int dh  = khw / 3 - 1;
        int dw  = khw - (khw / 3) * 3 - 1;
        #pragma unroll
        for (int r = 0; r < 2; r++) {
            int hh = h0[r] + dh, ww = w0[r] + dw;
            float4 v = make_float4(0.f, 0.f, 0.f, 0.f);
            if ((unsigned)hh < (unsigned)HD && (unsigned)ww < (unsigned)WD)
                v = *reinterpret_cast<const float4*>(
                        x + (((n0[r] * HD + hh) * WD + ww) * CI + c0 + a_k));
            ar[r] = v;
        }
        const float* bp = wy + (khw * CI + c0 + b_k) * CM + c_base + b_c;
        br[0] = *reinterpret_cast<const float4*>(bp);
        br[1] = *reinterpret_cast<const float4*>(bp + 8 * CM);
    };

    auto sstore = [&](int buf) {
        #pragma unroll
        for (int r = 0; r < 2; r++) {
            As[buf][a_k + 0][a_m + r * 64] = ar[r].x;
            As[buf][a_k + 1][a_m + r * 64] = ar[r].y;
            As[buf][a_k + 2][a_m + r * 64] = ar[r].z;
            As[buf][a_k + 3][a_m + r * 64] = ar[r].w;
            *reinterpret_cast<float4*>(&Bs[buf][b_k + r * 8][b_c]) = br[r];
        }
    };

    auto comp = [&](int buf) {
        #pragma unroll
        for (int kk = 0; kk < 16; kk++) {
            float af[8], bf[8];
            *reinterpret_cast<float4*>(af)     = *reinterpret_cast<const float4*>(&As[buf][kk][ty * 8]);
            *reinterpret_cast<float4*>(af + 4) = *reinterpret_cast<const float4*>(&As[buf][kk][ty * 8 + 4]);
            *reinterpret_cast<float4*>(bf)     = *reinterpret_cast<const float4*>(&Bs[buf][kk][tx * 8]);
            *reinterpret_cast<float4*>(bf + 4) = *reinterpret_cast<const float4*>(&Bs[buf][kk][tx * 8 + 4]);
            #pragma unroll
            for (int i = 0; i < 8; i++) asum[i] += af[i] * af[i];
            #pragma unroll
            for (int j = 0; j < 8; j++) bsum[j] += bf[j] * bf[j];
            #pragma unroll
            for (int i = 0; i < 8; i++)
                #pragma unroll
                for (int j = 0; j < 8; j++)
                    acc[i][j] += af[i] * bf[j];
        }
    };

    gload(0);
    sstore(0);
    __syncthreads();
    int buf = 0;
    for (int c = 0; c < NCH; c++) {
        if (c + 1 < NCH) gload(c + 1);
        comp(buf);
        if (c + 1 < NCH) {
            sstore(buf ^ 1);
            __syncthreads();
            buf ^= 1;
        }
    }

    // Epilogue: yat nonlinearity -> g_y
    const float alpha = alphap[0];
    const float scale = powf(16.0f / log1pf(256.0f), alpha);  // sqrt(256)=16
    #pragma unroll
    for (int i = 0; i < 8; i++) {
        size_t m = (size_t)(m_base + ty * 8 + i);
        float* dst = g_y + m * CM + c_base + tx * 8;
        float4 o0, o1;
        float v[8];
        #pragma unroll
        for (int j = 0; j < 8; j++) {
            float d    = acc[i][j];
            float dist = asum[i] + bsum[j] - 2.0f * d + 1e-5f;
            v[j] = d * d / dist * scale;
        }
        o0 = make_float4(v[0], v[1], v[2], v[3]);
        o1 = make_float4(v[4], v[5], v[6], v[7]);
        *reinterpret_cast<float4*>(dst)     = o0;
        *reinterpret_cast<float4*>(dst + 4) = o1;
    }
}

// ---------------------------------------------------------------------------
// Kernel 2: lin conv (K=2304 over g_y) + 1x1 residual (K=128 over x)
//           + fused 2x2 avg-pool epilogue.
// M-tile of 128 = one even-h row-pair (2 x 64 spatial), so pooling is
// intra-CTA: stage z in smem, reduce 2x2, write [n, h/2, 0..31, ctile].
// ---------------------------------------------------------------------------
__global__ __launch_bounds__(256)
void k2_lin(const float* __restrict__ x, const float* __restrict__ wl,
            const float* __restrict__ wp, float* __restrict__ out)
{
    extern __shared__ float sm[];
    // GEMM buffers: As [2][16][132] then Bs [2][16][132]
    float* Asb = sm;
    float* Bsb = sm + 2 * 16 * 132;
    // Epilogue reuses sm as z[128][132]

    const int tid    = threadIdx.x;
    const int m_base = blockIdx.y * 128;
    const int c_base = blockIdx.x * 128;

    const int a_m = tid >> 2;
    const int a_k = (tid & 3) * 4;
    const int b_k = tid >> 5;
    const int b_c = (tid & 31) * 4;
    const int ty  = tid >> 4, tx = tid & 15;

    float acc[8][8];
    #pragma unroll
    for (int i = 0; i < 8; i++)
        #pragma unroll
        for (int j = 0; j < 8; j++) acc[i][j] = 0.f;

    int n0[2], h0[2], w0[2];
    #pragma unroll
    for (int r = 0; r < 2; r++) {
        int m = m_base + a_m + r * 64;
        n0[r] = m >> 12; h0[r] = (m >> 6) & 63; w0[r] = m & 63;
    }

    const int NC1 = (9 * CM) / 16;   // 144 chunks for the 3x3x256 conv
    const int NCT = NC1 + CI / 16;   // +8 chunks for the 1x1 residual

    float4 ar[2], br[2];

    auto gload = [&](int chunk) {
        if (chunk < NC1) {
            int kb  = chunk << 4;
            int khw = kb >> 8;         // 0..8
            int c0  = kb & 255;
            int dh  = khw / 3 - 1;
            int dw  = khw - (khw / 3) * 3 - 1;
            #pragma unroll
            for (int r = 0; r < 2; r++) {
                int hh = h0[r] + dh, ww = w0[r] + dw;
                float4 v = make_float4(0.f, 0.f, 0.f, 0.f);
                if ((unsigned)hh < (unsigned)HD && (unsigned)ww < (unsigned)WD)
                    v = *reinterpret_cast<const float4*>(
                            g_y + ((size_t)((n0[r] * HD + hh) * WD + ww)) * CM + c0 + a_k);
                ar[r] = v;
            }
            const float* bp = wl + (size_t)((khw * CM + c0 + b_k)) * CM + c_base + b_c;
            br[0] = *reinterpret_cast<const float4*>(bp);
            br[1] = *reinterpret_cast<const float4*>(bp + 8 * CM);
        } else {
            int cc = (chunk - NC1) << 4;   // cin base 0..112
            #pragma unroll
            for (int r = 0; r < 2; r++) {
                size_t m = (size_t)(m_base + a_m + r * 64);
                ar[r] = *reinterpret_cast<const float4*>(x + m * CI + cc + a_k);
            }
            const float* bp = wp + (cc + b_k) * CM + c_base + b_c;
            br[0] = *reinterpret_cast<const float4*>(bp);
            br[1] = *reinterpret_cast<const float4*>(bp + 8 * CM);
        }
    };

    auto sstore = [&](int buf) {
        float (*As)[16][132] = reinterpret_cast<float (*)[16][132]>(Asb);
        float (*Bs)[16][132] = reinterpret_cast<float (*)[16][132]>(Bsb);
        #pragma unroll
        for (int r = 0; r < 2; r++) {
            As[buf][a_k + 0][a_m + r * 64] = ar[r].x;
            As[buf][a_k + 1][a_m + r * 64] = ar[r].y;
            As[buf][a_k + 2][a_m + r * 64] = ar[r].z;
            As[buf][a_k + 3][a_m + r * 64] = ar[r].w;
            *reinterpret_cast<float4*>(&Bs[buf][b_k + r * 8][b_c]) = br[r];
        }
    };

    auto comp = [&](int buf) {
        float (*As)[16][132] = reinterpret_cast<float (*)[16][132]>(Asb);
        float (*Bs)[16][132] = reinterpret_cast<float (*)[16][132]>(Bsb);
        #pragma unroll
        for (int kk = 0; kk < 16; kk++) {
            float af[8], bf[8];
            *reinterpret_cast<float4*>(af)     = *reinterpret_cast<const float4*>(&As[buf][kk][ty * 8]);
            *reinterpret_cast<float4*>(af + 4) = *reinterpret_cast<const float4*>(&As[buf][kk][ty * 8 + 4]);
            *reinterpret_cast<float4*>(bf)     = *reinterpret_cast<const float4*>(&Bs[buf][kk][tx * 8]);
            *reinterpret_cast<float4*>(bf + 4) = *reinterpret_cast<const float4*>(&Bs[buf][kk][tx * 8 + 4]);
            #pragma unroll
            for (int i = 0; i < 8; i++)
                #pragma unroll
                for (int j = 0; j < 8; j++)
                    acc[i][j] += af[i] * bf[j];
        }
    };

    gload(0);
    sstore(0);
    __syncthreads();
    int buf = 0;
    for (int c = 0; c < NCT; c++) {
        if (c + 1 < NCT) gload(c + 1);
        comp(buf);
        if (c + 1 < NCT) {
            sstore(buf ^ 1);
            __syncthreads();
            buf ^= 1;
        }
    }

    // --- Epilogue: stage z tile to smem, 2x2 avg-pool, write out ---
    __syncthreads();                       // everyone done with GEMM buffers
    #pragma unroll
    for (int i = 0; i < 8; i++) {
        int row = ty * 8 + i;              // 0..127 local spatial (hl*64 + w)
        *reinterpret_cast<float4*>(&sm[row * 132 + tx * 8]) =
            make_float4(acc[i][0], acc[i][1], acc[i][2], acc[i][3]);
        *reinterpret_cast<float4*>(&sm[row * 132 + tx * 8 + 4]) =
            make_float4(acc[i][4], acc[i][5], acc[i][6], acc[i][7]);
    }
    __syncthreads();

    const int n  = m_base >> 12;
    const int hp = ((m_base >> 6) & 63) >> 1;   // pooled h (m_base's h is even)

    #pragma unroll
    for (int it = 0; it < 4; it++) {
        int idx = tid + it * 256;          // 0..1023
        int pw  = idx >> 5;                // 0..31 pooled w
        int ch  = (idx & 31) * 4;          // 0..124 channel (float4)
        const float4 z0 = *reinterpret_cast<const float4*>(&sm[(2 * pw    ) * 132 + ch]);
        const float4 z1 = *reinterpret_cast<const float4*>(&sm[(2 * pw + 1) * 132 + ch]);
        const float4 z2 = *reinterpret_cast<const float4*>(&sm[(64 + 2 * pw    ) * 132 + ch]);
        const float4 z3 = *reinterpret_cast<const float4*>(&sm[(64 + 2 * pw + 1) * 132 + ch]);
        float4 o;
        o.x = 0.25f * (z0.x + z1.x + z2.x + z3.x);
        o.y = 0.25f * (z0.y + z1.y + z2.y + z3.y);
        o.z = 0.25f * (z0.z + z1.z + z2.z + z3.z);
        o.w = 0.25f * (z0.w + z1.w + z2.w + z3.w);
        size_t oi = ((size_t)((n * 32 + hp) * 32 + pw)) * 256 + c_base + ch;
        *reinterpret_cast<float4*>(out + oi) = o;
    }
}

// ---------------------------------------------------------------------------
extern "C" void kernel_launch(void* const* d_in, const int* in_sizes, int n_in,
                              void* d_out, int out_size)
{
    const float* x  = (const float*)d_in[0];   // [32,64,64,128]
    const float* wy = (const float*)d_in[1];   // [3,3,128,256]
    const float* al = (const float*)d_in[2];   // [1]
    const float* wl = (const float*)d_in[3];   // [3,3,256,256]
    const float* wp = (const float*)d_in[4];   // [1,1,128,256]
    float* out = (float*)d_out;                // [32,32,32,256]

    const int smem2 = 128 * 132 * 4;           // 67584 B (> 48K, opt-in)
    cudaFuncSetAttribute(k2_lin, cudaFuncAttributeMaxDynamicSharedMemorySize, smem2);

    dim3 grid(2, 1024);   // (cout tiles, M tiles)
    k1_yat<<<grid, 256>>>(x, wy, al);
    k2_lin<<<grid, 256, smem2>>>(x, wl, wp, out);
}